// round 2
// baseline (speedup 1.0000x reference)
#include <cuda_runtime.h>
#include <cstdint>

// ---------------- problem dims (fixed) ----------------
#define TOKENS (8*4096)   // B*L = 32768
#define DMODEL 256
#define DINNER 384
#define DSTATE 8
#define NXZ (3*DINNER)    // 1152

// ---------------- scratch (static device, no allocs) ----------------
__device__ float g_xn[(size_t)TOKENS * DMODEL];   // layernorm output
__device__ float g_xz[(size_t)TOKENS * NXZ];      // silu(x_proj), silu(z), dt_in
__device__ float g_dt[(size_t)TOKENS * DINNER];   // softplus(dt)
__device__ float g_y [(size_t)TOKENS * DINNER];   // scan output (pre out-proj)

// ---------------- helpers ----------------
__device__ __forceinline__ uint32_t f2tf(float f) {
    uint32_t r;
    asm("cvt.rna.tf32.f32 %0, %1;" : "=r"(r) : "f"(f));
    return r;
}

__device__ __forceinline__ void mma_tf32(float* d, const uint32_t* a, const uint32_t* b) {
    asm volatile(
        "mma.sync.aligned.m16n8k8.row.col.f32.tf32.tf32.f32 "
        "{%0,%1,%2,%3}, {%4,%5,%6,%7}, {%8,%9}, {%0,%1,%2,%3};\n"
        : "+f"(d[0]), "+f"(d[1]), "+f"(d[2]), "+f"(d[3])
        : "r"(a[0]), "r"(a[1]), "r"(a[2]), "r"(a[3]),
          "r"(b[0]), "r"(b[1]));
}

__device__ __forceinline__ void cp_async16(void* smem_dst, const void* gmem_src) {
    uint32_t dst = (uint32_t)__cvta_generic_to_shared(smem_dst);
    asm volatile("cp.async.cg.shared.global [%0], [%1], 16;\n"
                 :: "r"(dst), "l"(gmem_src));
}

// ---------------- LayerNorm: one warp per token ----------------
__global__ __launch_bounds__(256)
void ln_kernel(const float* __restrict__ x, const float* __restrict__ gamma,
               const float* __restrict__ beta, float* __restrict__ out) {
    int warp = threadIdx.x >> 5;
    int lane = threadIdx.x & 31;
    size_t tok = (size_t)blockIdx.x * 8 + warp;
    const float* xr = x + tok * DMODEL;
    int k = lane * 8;
    float4 v0 = *reinterpret_cast<const float4*>(xr + k);
    float4 v1 = *reinterpret_cast<const float4*>(xr + k + 4);
    float s = v0.x + v0.y + v0.z + v0.w + v1.x + v1.y + v1.z + v1.w;
    float q = v0.x*v0.x + v0.y*v0.y + v0.z*v0.z + v0.w*v0.w
            + v1.x*v1.x + v1.y*v1.y + v1.z*v1.z + v1.w*v1.w;
    #pragma unroll
    for (int off = 16; off; off >>= 1) {
        s += __shfl_xor_sync(0xffffffffu, s, off);
        q += __shfl_xor_sync(0xffffffffu, q, off);
    }
    float mu   = s * (1.0f / DMODEL);
    float var  = q * (1.0f / DMODEL) - mu * mu;
    float rstd = rsqrtf(var + 1e-5f);
    float* orow = out + tok * DMODEL;
    float4 r0, r1;
    r0.x = (v0.x - mu) * rstd * gamma[k+0] + beta[k+0];
    r0.y = (v0.y - mu) * rstd * gamma[k+1] + beta[k+1];
    r0.z = (v0.z - mu) * rstd * gamma[k+2] + beta[k+2];
    r0.w = (v0.w - mu) * rstd * gamma[k+3] + beta[k+3];
    r1.x = (v1.x - mu) * rstd * gamma[k+4] + beta[k+4];
    r1.y = (v1.y - mu) * rstd * gamma[k+5] + beta[k+5];
    r1.z = (v1.z - mu) * rstd * gamma[k+6] + beta[k+6];
    r1.w = (v1.w - mu) * rstd * gamma[k+7] + beta[k+7];
    *reinterpret_cast<float4*>(orow + k)     = r0;
    *reinterpret_cast<float4*>(orow + k + 4) = r1;
}

// ---------------- tf32 GEMM: C[M,N] = epi(A[M,K] @ W[N,K]^T + bias) ----------------
// BM=128 BN=128 BK=32, 256 threads, warp grid 2(M) x 4(N), warp tile 64x32.
// 2-stage cp.async double-buffered pipeline.
// EPI: 0 = xz (silu on cols < 2*DINNER), 1 = softplus, 2 = +bias +residual
#define BM 128
#define BN 128
#define BK 32
#define BKP (BK + 4)   // pad 4 floats -> conflict-free fragment loads

template<int EPI>
__global__ __launch_bounds__(256, 2)
void gemm_tf32(const float* __restrict__ A, int lda, int aoff,
               const float* __restrict__ W, int K,
               const float* __restrict__ bias,
               float* __restrict__ C, int ldc,
               const float* __restrict__ resid) {
    extern __shared__ float sm[];
    float* As = sm;                    // [2][BM][BKP]
    float* Bs = sm + 2 * BM * BKP;     // [2][BN][BKP]

    int tid = threadIdx.x;
    int wid = tid >> 5, lane = tid & 31;
    int warp_m = wid & 1;        // 0..1 -> 64 rows each
    int warp_n = wid >> 1;       // 0..3 -> 32 cols each
    int bm = blockIdx.y * BM;
    int bn = blockIdx.x * BN;

    int srow = tid >> 3;          // 0..31
    int scol = (tid & 7) * 4;     // 0..28

    const float* Aptr = A + (size_t)bm * lda + aoff;
    const float* Wptr = W + (size_t)bn * K;

    float acc[4][4][4] = {};
    int r0 = lane >> 2, c0 = lane & 3;
    int nk = K / BK;

    // prologue: stage tile 0 into buf 0
    {
        float* as = As;
        float* bs = Bs;
        #pragma unroll
        for (int i = 0; i < 4; i++) {
            int row = srow + i * 32;
            cp_async16(&as[row * BKP + scol], Aptr + (size_t)row * lda + scol);
            cp_async16(&bs[row * BKP + scol], Wptr + (size_t)row * K + scol);
        }
        asm volatile("cp.async.commit_group;\n");
    }

    for (int kt = 0; kt < nk; kt++) {
        int buf = kt & 1;
        if (kt + 1 < nk) {
            int ke = (kt + 1) * BK;
            float* as = As + (buf ^ 1) * BM * BKP;
            float* bs = Bs + (buf ^ 1) * BN * BKP;
            #pragma unroll
            for (int i = 0; i < 4; i++) {
                int row = srow + i * 32;
                cp_async16(&as[row * BKP + scol], Aptr + (size_t)row * lda + ke + scol);
                cp_async16(&bs[row * BKP + scol], Wptr + (size_t)row * K + ke + scol);
            }
            asm volatile("cp.async.commit_group;\n");
            asm volatile("cp.async.wait_group 1;\n");
        } else {
            asm volatile("cp.async.wait_group 0;\n");
        }
        __syncthreads();

        const float* as = As + buf * BM * BKP + (warp_m * 64 + r0) * BKP;
        const float* bs = Bs + buf * BN * BKP + (warp_n * 32 + r0) * BKP;
        #pragma unroll
        for (int k8 = 0; k8 < BK / 8; k8++) {
            int kc = k8 * 8 + c0;
            uint32_t af[4][4], bf[4][2];
            #pragma unroll
            for (int mi = 0; mi < 4; mi++) {
                af[mi][0] = f2tf(as[(mi * 16    ) * BKP + kc    ]);
                af[mi][1] = f2tf(as[(mi * 16 + 8) * BKP + kc    ]);
                af[mi][2] = f2tf(as[(mi * 16    ) * BKP + kc + 4]);
                af[mi][3] = f2tf(as[(mi * 16 + 8) * BKP + kc + 4]);
            }
            #pragma unroll
            for (int ni = 0; ni < 4; ni++) {
                bf[ni][0] = f2tf(bs[(ni * 8) * BKP + kc    ]);
                bf[ni][1] = f2tf(bs[(ni * 8) * BKP + kc + 4]);
            }
            #pragma unroll
            for (int mi = 0; mi < 4; mi++)
                #pragma unroll
                for (int ni = 0; ni < 4; ni++)
                    mma_tf32(acc[mi][ni], af[mi], bf[ni]);
        }
        __syncthreads();
    }

    // epilogue
    #pragma unroll
    for (int mi = 0; mi < 4; mi++) {
        #pragma unroll
        for (int ni = 0; ni < 4; ni++) {
            int gr = bm + warp_m * 64 + mi * 16 + r0;
            int gc = bn + warp_n * 32 + ni * 8 + c0 * 2;
            #pragma unroll
            for (int rg = 0; rg < 4; rg++) {
                int row = gr + (rg >> 1) * 8;
                int col = gc + (rg & 1);
                float v = acc[mi][ni][rg] + bias[col];
                if (EPI == 0) {
                    if (col < 2 * DINNER) v = v / (1.0f + __expf(-v));   // silu
                } else if (EPI == 1) {
                    v = fmaxf(v, 0.0f) + log1pf(__expf(-fabsf(v)));      // softplus
                } else {
                    v += resid[(size_t)row * ldc + col];
                }
                C[(size_t)row * ldc + col] = v;
            }
        }
    }
}

#define GEMM_SMEM (2 * (BM + BN) * BKP * 4)

// ---------------- chunked scan + gating ----------------
// thread handles 4 consecutive di for one 32-token chunk (h resets per chunk)
__global__ __launch_bounds__(192)
void scan_kernel(const float* __restrict__ xz, const float* __restrict__ dtb,
                 const float* __restrict__ A_log, const float* __restrict__ Dvec,
                 float* __restrict__ y) {
    int di = threadIdx.x * 4;                                   // 0..380
    size_t tok0 = ((size_t)blockIdx.x * 2 + threadIdx.y) * 32;  // chunk base token
    float4 nA[DSTATE];
    #pragma unroll
    for (int s = 0; s < DSTATE; s++) {
        nA[s].x = -__expf(__ldg(&A_log[(di + 0) * DSTATE + s]));
        nA[s].y = -__expf(__ldg(&A_log[(di + 1) * DSTATE + s]));
        nA[s].z = -__expf(__ldg(&A_log[(di + 2) * DSTATE + s]));
        nA[s].w = -__expf(__ldg(&A_log[(di + 3) * DSTATE + s]));
    }
    float4 Dv = *reinterpret_cast<const float4*>(&Dvec[di]);
    float4 h[DSTATE];
    #pragma unroll
    for (int s = 0; s < DSTATE; s++) h[s] = make_float4(0.f, 0.f, 0.f, 0.f);

    #pragma unroll 2
    for (int t = 0; t < 32; t++) {
        size_t tok = tok0 + t;
        float4 xp  = *reinterpret_cast<const float4*>(&xz[tok * NXZ + di]);
        float4 zv  = *reinterpret_cast<const float4*>(&xz[tok * NXZ + DINNER + di]);
        float4 dtv = *reinterpret_cast<const float4*>(&dtb[tok * DINNER + di]);
        float4 ys = make_float4(0.f, 0.f, 0.f, 0.f);
        #pragma unroll
        for (int s = 0; s < DSTATE; s++) {
            h[s].x = fmaf(h[s].x, __expf(dtv.x * nA[s].x), xp.x); ys.x += h[s].x;
            h[s].y = fmaf(h[s].y, __expf(dtv.y * nA[s].y), xp.y); ys.y += h[s].y;
            h[s].z = fmaf(h[s].z, __expf(dtv.z * nA[s].z), xp.z); ys.z += h[s].z;
            h[s].w = fmaf(h[s].w, __expf(dtv.w * nA[s].w), xp.w); ys.w += h[s].w;
        }
        float4 o;
        o.x = fmaf(ys.x, zv.x, xp.x * Dv.x);
        o.y = fmaf(ys.y, zv.y, xp.y * Dv.y);
        o.z = fmaf(ys.z, zv.z, xp.z * Dv.z);
        o.w = fmaf(ys.w, zv.w, xp.w * Dv.w);
        *reinterpret_cast<float4*>(&y[tok * DINNER + di]) = o;
    }
}

// ---------------- launch ----------------
extern "C" void kernel_launch(void* const* d_in, const int* in_sizes, int n_in,
                              void* d_out, int out_size) {
    (void)in_sizes; (void)n_in; (void)out_size;
    const float* x     = (const float*)d_in[0];
    const float* gamma = (const float*)d_in[1];
    const float* beta  = (const float*)d_in[2];
    const float* W_in  = (const float*)d_in[3];
    const float* b_in  = (const float*)d_in[4];
    const float* W_dt  = (const float*)d_in[5];
    const float* b_dt  = (const float*)d_in[6];
    const float* A_log = (const float*)d_in[7];
    const float* D_vec = (const float*)d_in[8];
    const float* W_out = (const float*)d_in[9];
    const float* b_out = (const float*)d_in[10];
    float* out = (float*)d_out;

    float *xn, *xz, *dt, *y;
    cudaGetSymbolAddress((void**)&xn, g_xn);
    cudaGetSymbolAddress((void**)&xz, g_xz);
    cudaGetSymbolAddress((void**)&dt, g_dt);
    cudaGetSymbolAddress((void**)&y,  g_y);

    static bool attr_set = false;
    if (!attr_set) {
        cudaFuncSetAttribute(gemm_tf32<0>, cudaFuncAttributeMaxDynamicSharedMemorySize, GEMM_SMEM);
        cudaFuncSetAttribute(gemm_tf32<1>, cudaFuncAttributeMaxDynamicSharedMemorySize, GEMM_SMEM);
        cudaFuncSetAttribute(gemm_tf32<2>, cudaFuncAttributeMaxDynamicSharedMemorySize, GEMM_SMEM);
        attr_set = true;
    }

    // 1) layernorm
    ln_kernel<<<TOKENS / 8, 256>>>(x, gamma, beta, xn);

    // 2) xz = xn @ W_in^T + b_in, silu on x_proj and z parts
    gemm_tf32<0><<<dim3(NXZ / BN, TOKENS / BM), 256, GEMM_SMEM>>>(
        xn, DMODEL, 0, W_in, DMODEL, b_in, xz, NXZ, nullptr);

    // 3) dt = softplus(dt_in @ W_dt^T + b_dt); dt_in = xz cols [768,1152)
    gemm_tf32<1><<<dim3(DINNER / BN, TOKENS / BM), 256, GEMM_SMEM>>>(
        xz, NXZ, 2 * DINNER, W_dt, DINNER, b_dt, dt, DINNER, nullptr);

    // 4) chunked SSM scan + gating (y = scan*z + x_proj*D)
    scan_kernel<<<TOKENS / 64, dim3(96, 2)>>>(xz, dt, A_log, D_vec, y);

    // 5) out = y @ W_out^T + b_out + residual
    gemm_tf32<2><<<dim3(DMODEL / BN, TOKENS / BM), 256, GEMM_SMEM>>>(
        y, DINNER, 0, W_out, DINNER, b_out, out, DMODEL, x);
}

// round 5
// speedup vs baseline: 2.4278x; 2.4278x over previous
#include <cuda_runtime.h>
#include <cuda_fp16.h>
#include <cstdint>

// ---------------- problem dims (fixed) ----------------
#define TOKENS (8*4096)   // B*L = 32768
#define DMODEL 256
#define DINNER 384
#define DSTATE 8
#define NXZ (3*DINNER)    // 1152

// ---------------- scratch (static device, no allocs) ----------------
__device__ __half g_xn[(size_t)TOKENS * DMODEL];   // layernorm out (fp16)
__device__ __half g_xz[(size_t)TOKENS * NXZ];      // silu(x_proj), silu(z), dt_in (fp16)
__device__ __half g_dt[(size_t)TOKENS * DINNER];   // softplus(dt) (fp16)
__device__ __half g_y [(size_t)TOKENS * DINNER];   // scan out (fp16)
__device__ __half g_wi[(size_t)NXZ * DMODEL];      // W_in fp16
__device__ __half g_wd[(size_t)DINNER * DINNER];   // W_dt fp16
__device__ __half g_wo[(size_t)DMODEL * DINNER];   // W_out fp16

// ---------------- helpers ----------------
__device__ __forceinline__ void mma_f16(float* d, const uint32_t* a, const uint32_t* b) {
    asm volatile(
        "mma.sync.aligned.m16n8k16.row.col.f32.f16.f16.f32 "
        "{%0,%1,%2,%3}, {%4,%5,%6,%7}, {%8,%9}, {%0,%1,%2,%3};\n"
        : "+f"(d[0]), "+f"(d[1]), "+f"(d[2]), "+f"(d[3])
        : "r"(a[0]), "r"(a[1]), "r"(a[2]), "r"(a[3]),
          "r"(b[0]), "r"(b[1]));
}
__device__ __forceinline__ void cp_async16(void* smem_dst, const void* gmem_src) {
    uint32_t dst = (uint32_t)__cvta_generic_to_shared(smem_dst);
    asm volatile("cp.async.cg.shared.global [%0], [%1], 16;" :: "r"(dst), "l"(gmem_src));
}

// ---------------- weight conversion: fp32 -> fp16 ----------------
__global__ __launch_bounds__(256)
void cvtw_kernel(const float* __restrict__ w, __half* __restrict__ o, int n) {
    int i = (blockIdx.x * 256 + threadIdx.x) * 4;
    if (i < n) {
        float4 v = *reinterpret_cast<const float4*>(&w[i]);
        *reinterpret_cast<__half2*>(&o[i])     = __floats2half2_rn(v.x, v.y);
        *reinterpret_cast<__half2*>(&o[i + 2]) = __floats2half2_rn(v.z, v.w);
    }
}

// ---------------- LayerNorm: one warp per token, fp16 out ----------------
__global__ __launch_bounds__(256)
void ln_kernel(const float* __restrict__ x, const float* __restrict__ gamma,
               const float* __restrict__ beta, __half* __restrict__ out) {
    int warp = threadIdx.x >> 5;
    int lane = threadIdx.x & 31;
    size_t tok = (size_t)blockIdx.x * 8 + warp;
    const float* xr = x + tok * DMODEL;
    int k = lane * 8;
    float4 v0 = *reinterpret_cast<const float4*>(xr + k);
    float4 v1 = *reinterpret_cast<const float4*>(xr + k + 4);
    float s = v0.x + v0.y + v0.z + v0.w + v1.x + v1.y + v1.z + v1.w;
    float q = v0.x*v0.x + v0.y*v0.y + v0.z*v0.z + v0.w*v0.w
            + v1.x*v1.x + v1.y*v1.y + v1.z*v1.z + v1.w*v1.w;
    #pragma unroll
    for (int off = 16; off; off >>= 1) {
        s += __shfl_xor_sync(0xffffffffu, s, off);
        q += __shfl_xor_sync(0xffffffffu, q, off);
    }
    float mu   = s * (1.0f / DMODEL);
    float var  = q * (1.0f / DMODEL) - mu * mu;
    float rstd = rsqrtf(var + 1e-5f);
    __half2 h[4];
    h[0] = __floats2half2_rn((v0.x-mu)*rstd*gamma[k+0]+beta[k+0], (v0.y-mu)*rstd*gamma[k+1]+beta[k+1]);
    h[1] = __floats2half2_rn((v0.z-mu)*rstd*gamma[k+2]+beta[k+2], (v0.w-mu)*rstd*gamma[k+3]+beta[k+3]);
    h[2] = __floats2half2_rn((v1.x-mu)*rstd*gamma[k+4]+beta[k+4], (v1.y-mu)*rstd*gamma[k+5]+beta[k+5]);
    h[3] = __floats2half2_rn((v1.z-mu)*rstd*gamma[k+6]+beta[k+6], (v1.w-mu)*rstd*gamma[k+7]+beta[k+7]);
    *reinterpret_cast<uint4*>(out + tok * DMODEL + k) = *reinterpret_cast<uint4*>(h);
}

// ============ fp16 GEMM: C[M,N] = epi(A[M,K] @ W[N,K]^T + bias) ============
// BM=128 BN=128 BK=32(halves), 256 threads, warps 2(M)x4(N), warp tile 64x32.
// 3-stage cp.async ring. Padded smem rows (40 halves) -> conflict-free LDS.32.
// EPI: 0 = silu if bn < 2*DINNER (half out), 1 = softplus (half out), 2 = +residual (float out)
#define BM 128
#define BN 128
#define BK 32
#define BKP 40                                     // halves per padded row (80B, 16B-mult)
#define NSTAGE 3
#define STAGE_H ((BM + BN) * BKP)                  // halves per stage = 10240 (20KB)
#define GEMM_SMEM (NSTAGE * STAGE_H * 2)           // 61440 B

template<int EPI>
__global__ __launch_bounds__(256, 2)
void gemm_f16(const __half* __restrict__ A, int lda, int aoff,
              const __half* __restrict__ W, int K,
              const float* __restrict__ bias,
              void* __restrict__ Cv, int ldc,
              const float* __restrict__ resid) {
    extern __shared__ __half smh[];

    int tid = threadIdx.x;
    int wid = tid >> 5, lane = tid & 31;
    int warp_m = wid & 1;        // 0..1 -> 64 rows
    int warp_n = wid >> 1;       // 0..3 -> 32 cols
    int bm = blockIdx.y * BM;
    int bn = blockIdx.x * BN;

    const __half* Ap = A + (size_t)bm * lda + aoff;
    const __half* Wp = W + (size_t)bn * K;
    int nk = K / BK;

    // stage one BK tile: A 128x32h + W 128x32h, each row = 4 x 16B chunks
    auto stage = [&](int s, int kc) {
        __half* sA = smh + s * STAGE_H;
        __half* sB = sA + BM * BKP;
        #pragma unroll
        for (int i = 0; i < 2; i++) {
            int j = tid + i * 256;            // 0..511
            int row = j >> 2, c = j & 3;
            cp_async16(sA + row * BKP + c * 8, Ap + (size_t)row * lda + kc + c * 8);
        }
        #pragma unroll
        for (int i = 0; i < 2; i++) {
            int j = tid + i * 256;
            int row = j >> 2, c = j & 3;
            cp_async16(sB + row * BKP + c * 8, Wp + (size_t)row * K + kc + c * 8);
        }
        asm volatile("cp.async.commit_group;" ::: "memory");
    };

    #pragma unroll
    for (int s = 0; s < NSTAGE; s++) stage(s, s * BK);

    float acc[4][4][4] = {};
    int g = lane >> 2, c2 = (lane & 3) * 2;

    for (int kt = 0; kt < nk; kt++) {
        int buf = kt % NSTAGE;
        int rem = nk - 1 - kt;
        if (rem >= 2)      asm volatile("cp.async.wait_group 2;" ::: "memory");
        else if (rem == 1) asm volatile("cp.async.wait_group 1;" ::: "memory");
        else               asm volatile("cp.async.wait_group 0;" ::: "memory");
        __syncthreads();

        const __half* as = smh + buf * STAGE_H + (warp_m * 64 + g) * BKP;
        const __half* bs = smh + buf * STAGE_H + BM * BKP + (warp_n * 32 + g) * BKP;
        #pragma unroll
        for (int k16 = 0; k16 < BK / 16; k16++) {
            int kb = k16 * 16 + c2;
            uint32_t afr[4][4], bfr[4][2];
            #pragma unroll
            for (int mt = 0; mt < 4; mt++) {
                const __half* ap = as + mt * 16 * BKP;
                afr[mt][0] = *reinterpret_cast<const uint32_t*>(&ap[kb]);
                afr[mt][1] = *reinterpret_cast<const uint32_t*>(&ap[8 * BKP + kb]);
                afr[mt][2] = *reinterpret_cast<const uint32_t*>(&ap[kb + 8]);
                afr[mt][3] = *reinterpret_cast<const uint32_t*>(&ap[8 * BKP + kb + 8]);
            }
            #pragma unroll
            for (int nt = 0; nt < 4; nt++) {
                const __half* bp = bs + nt * 8 * BKP;
                bfr[nt][0] = *reinterpret_cast<const uint32_t*>(&bp[kb]);
                bfr[nt][1] = *reinterpret_cast<const uint32_t*>(&bp[kb + 8]);
            }
            #pragma unroll
            for (int mt = 0; mt < 4; mt++)
                #pragma unroll
                for (int nt = 0; nt < 4; nt++)
                    mma_f16(acc[mt][nt], afr[mt], bfr[nt]);
        }
        __syncthreads();
        if (kt + NSTAGE < nk) stage(buf, (kt + NSTAGE) * BK);
    }

    // ---------------- epilogue ----------------
    bool do_silu = (EPI == 0) && (bn < 2 * DINNER);
    #pragma unroll
    for (int mt = 0; mt < 4; mt++) {
        #pragma unroll
        for (int nt = 0; nt < 4; nt++) {
            int row = bm + warp_m * 64 + mt * 16 + g;
            int col = bn + warp_n * 32 + nt * 8 + c2;
            float bv0 = bias[col], bv1 = bias[col + 1];
            float v[4];
            v[0] = acc[mt][nt][0] + bv0; v[1] = acc[mt][nt][1] + bv1;
            v[2] = acc[mt][nt][2] + bv0; v[3] = acc[mt][nt][3] + bv1;
            if (EPI == 0) {
                if (do_silu) {
                    #pragma unroll
                    for (int i = 0; i < 4; i++) v[i] = v[i] / (1.0f + __expf(-v[i]));
                }
            } else if (EPI == 1) {
                #pragma unroll
                for (int i = 0; i < 4; i++)
                    v[i] = fmaxf(v[i], 0.0f) + log1pf(__expf(-fabsf(v[i])));
            }
            if (EPI < 2) {
                __half* C = (__half*)Cv;
                *reinterpret_cast<__half2*>(&C[(size_t)row * ldc + col])
                    = __floats2half2_rn(v[0], v[1]);
                *reinterpret_cast<__half2*>(&C[(size_t)(row + 8) * ldc + col])
                    = __floats2half2_rn(v[2], v[3]);
            } else {
                float* C = (float*)Cv;
                float2 r0 = *reinterpret_cast<const float2*>(&resid[(size_t)row * ldc + col]);
                float2 r1 = *reinterpret_cast<const float2*>(&resid[(size_t)(row + 8) * ldc + col]);
                float2 o0 = make_float2(v[0] + r0.x, v[1] + r0.y);
                float2 o1 = make_float2(v[2] + r1.x, v[3] + r1.y);
                *reinterpret_cast<float2*>(&C[(size_t)row * ldc + col]) = o0;
                *reinterpret_cast<float2*>(&C[(size_t)(row + 8) * ldc + col]) = o1;
            }
        }
    }
}

// ---------------- chunked scan + gating (fp16 I/O) ----------------
__global__ __launch_bounds__(128)
void scan_kernel(const __half* __restrict__ xz, const __half* __restrict__ dtb,
                 const float* __restrict__ A_log, const float* __restrict__ Dvec,
                 __half* __restrict__ y) {
    int di = blockIdx.x * 128 + threadIdx.x;           // 0..383
    size_t tok0 = (size_t)blockIdx.y * 32;             // chunk base token
    float nA[DSTATE];
    #pragma unroll
    for (int s = 0; s < DSTATE; s++)
        nA[s] = -__expf(A_log[di * DSTATE + s]);
    float Dv = Dvec[di];
    float h[DSTATE] = {};
    #pragma unroll 4
    for (int t = 0; t < 32; t++) {
        size_t tok = tok0 + t;
        float xp  = __half2float(xz[tok * NXZ + di]);
        float zv  = __half2float(xz[tok * NXZ + DINNER + di]);
        float dtv = __half2float(dtb[tok * DINNER + di]);
        float ys = 0.0f;
        #pragma unroll
        for (int s = 0; s < DSTATE; s++) {
            h[s] = fmaf(h[s], __expf(dtv * nA[s]), xp);
            ys += h[s];
        }
        y[tok * DINNER + di] = __float2half(fmaf(ys, zv, xp * Dv));
    }
}

// ---------------- launch ----------------
extern "C" void kernel_launch(void* const* d_in, const int* in_sizes, int n_in,
                              void* d_out, int out_size) {
    (void)in_sizes; (void)n_in; (void)out_size;
    const float* x     = (const float*)d_in[0];
    const float* gamma = (const float*)d_in[1];
    const float* beta  = (const float*)d_in[2];
    const float* W_in  = (const float*)d_in[3];
    const float* b_in  = (const float*)d_in[4];
    const float* W_dt  = (const float*)d_in[5];
    const float* b_dt  = (const float*)d_in[6];
    const float* A_log = (const float*)d_in[7];
    const float* D_vec = (const float*)d_in[8];
    const float* W_out = (const float*)d_in[9];
    const float* b_out = (const float*)d_in[10];
    float* out = (float*)d_out;

    __half *xn, *xz, *dt, *y, *wi, *wd, *wo;
    cudaGetSymbolAddress((void**)&xn, g_xn);
    cudaGetSymbolAddress((void**)&xz, g_xz);
    cudaGetSymbolAddress((void**)&dt, g_dt);
    cudaGetSymbolAddress((void**)&y,  g_y);
    cudaGetSymbolAddress((void**)&wi, g_wi);
    cudaGetSymbolAddress((void**)&wd, g_wd);
    cudaGetSymbolAddress((void**)&wo, g_wo);

    cudaFuncSetAttribute(gemm_f16<0>, cudaFuncAttributeMaxDynamicSharedMemorySize, GEMM_SMEM);
    cudaFuncSetAttribute(gemm_f16<1>, cudaFuncAttributeMaxDynamicSharedMemorySize, GEMM_SMEM);
    cudaFuncSetAttribute(gemm_f16<2>, cudaFuncAttributeMaxDynamicSharedMemorySize, GEMM_SMEM);

    // 0) weight conversions (fp32 -> fp16)
    cvtw_kernel<<<(NXZ * DMODEL / 4 + 255) / 256, 256>>>(W_in, wi, NXZ * DMODEL);
    cvtw_kernel<<<(DINNER * DINNER / 4 + 255) / 256, 256>>>(W_dt, wd, DINNER * DINNER);
    cvtw_kernel<<<(DMODEL * DINNER / 4 + 255) / 256, 256>>>(W_out, wo, DMODEL * DINNER);

    // 1) layernorm (fp16 out)
    ln_kernel<<<TOKENS / 8, 256>>>(x, gamma, beta, xn);

    // 2) xz = xn @ W_in^T + b_in, silu on x_proj and z parts
    gemm_f16<0><<<dim3(NXZ / BN, TOKENS / BM), 256, GEMM_SMEM>>>(
        xn, DMODEL, 0, wi, DMODEL, b_in, xz, NXZ, nullptr);

    // 3) dt = softplus(dt_in @ W_dt^T + b_dt); dt_in = xz cols [768,1152)
    gemm_f16<1><<<dim3(DINNER / BN, TOKENS / BM), 256, GEMM_SMEM>>>(
        xz, NXZ, 2 * DINNER, wd, DINNER, b_dt, dt, DINNER, nullptr);

    // 4) chunked SSM scan + gating
    scan_kernel<<<dim3(DINNER / 128, TOKENS / 32), 128>>>(xz, dt, A_log, D_vec, y);

    // 5) out = y @ W_out^T + b_out + residual
    gemm_f16<2><<<dim3(DMODEL / BN, TOKENS / BM), 256, GEMM_SMEM>>>(
        y, DINNER, 0, wo, DINNER, b_out, out, DMODEL, x);
}